// round 16
// baseline (speedup 1.0000x reference)
#include <cuda_runtime.h>
#include <cuda_bf16.h>
#include <cuda_fp16.h>
#include <cstdint>
#include <cstddef>

// ---------------- problem constants ----------------
#define NNODE  150000
#define N64    (NNODE * 64)          // 9,600,000
#define TDIM   384
#define BATCH  1024
#define SEQ    20
#define NPRED  20
#define EMAX   1000000
#define SEMAX  200000
#define NBINS  (2 * NNODE + 2)       // big rowptr [0..N], small [N+1..2N+1]
#define NSCANB ((NBINS + 1023) / 1024)

// ---------------- scratch (device globals) ----------------
__device__ __half g_xwh[8ull * N64];         // xw_r = x @ W_r  [N][8][64] fp16 (154 MB)
__device__ float g_agg[N64];                 // root + bias      [N][64]
__device__ float g_cs[(size_t)NNODE * TDIM]; // concat of 6 states [N][384]
__device__ float g_ssum[BATCH * TDIM];
__device__ float g_uv[BATCH * TDIM];
// all 6 layers' bf16 W images: per layer [hi 320x72][lo 320x72] halfs
__device__ unsigned short g_wimg_all[6][2 * 320 * 72];
// CSR structures (both graphs share one packed edge array)
__device__ int g_rowptr[NBINS];
__device__ int g_cursor[NBINS];
__device__ int g_blocksum[NSCANB + 1];
__device__ unsigned int g_epack[EMAX + SEMAX];

// ---------------- helpers ----------------
__device__ __forceinline__ unsigned long long dup_f32x2(float v) {
    unsigned long long a;
    asm("mov.b64 %0, {%1, %1};" : "=l"(a) : "f"(v));
    return a;
}
__device__ __forceinline__ unsigned long long pack_f32x2(float x, float y) {
    unsigned long long a;
    asm("mov.b64 %0, {%1, %2};" : "=l"(a) : "f"(x), "f"(y));
    return a;
}
__device__ __forceinline__ void ffma2(unsigned long long& acc,
                                      unsigned long long a, unsigned long long b) {
    asm("fma.rn.f32x2 %0, %1, %2, %0;" : "+l"(acc) : "l"(a), "l"(b));
}

// mma.sync m16n8k16 bf16 (baseline PTX, works on compute_103)
#define MMA_BF16(d, a, b0_, b1_) \
    asm volatile("mma.sync.aligned.m16n8k16.row.col.f32.bf16.bf16.f32 " \
        "{%0,%1,%2,%3}, {%4,%5,%6,%7}, {%8,%9}, {%0,%1,%2,%3};" \
        : "+f"((d)[0]), "+f"((d)[1]), "+f"((d)[2]), "+f"((d)[3]) \
        : "r"((a)[0]), "r"((a)[1]), "r"((a)[2]), "r"((a)[3]), \
          "r"(b0_), "r"(b1_))

// smem byte offsets for tc_dense (stride 144B per row everywhere)
#define SM_XHI   0
#define SM_XLO   (256 * 144)             // 36864
#define SM_WHI   (2 * 256 * 144)         // 73728
#define SM_WLO   (SM_WHI + 320 * 144)    // 119808
#define SM_COMP  (SM_WLO + 320 * 144)    // 165888
#define SM_BIASO (SM_COMP + 128)         // 166016
#define TC_SMEM  (SM_BIASO + 256)        // 166272

// =====================================================================
// w_prep_all: bake all 6 layers' W = [basis0..3 | root] bf16 hi/lo
// images, layout [n][k] stride 72 halfs.
// =====================================================================
__global__ __launch_bounds__(256) void w_prep_all(
    const float* __restrict__ basis, const float* __restrict__ root,
    const float* __restrict__ sbasis, const float* __restrict__ sroot)
{
    int idx = blockIdx.x * 256 + threadIdx.x;      // 0..122879
    if (idx >= 6 * 320 * 64) return;
    int l   = idx / (320 * 64);
    int rem = idx - l * (320 * 64);
    int n = rem >> 6;
    int k = rem & 63;
    const float* B = (l < 3) ? basis + l * 16384 : sbasis + (l - 3) * 16384;
    const float* R = (l < 3) ? root + l * 4096  : sroot + (l - 3) * 4096;
    float v = (n < 256) ? B[(n >> 6) * 4096 + k * 64 + (n & 63)]
                        : R[k * 64 + (n - 256)];
    __nv_bfloat16 h = __float2bfloat16(v);
    __nv_bfloat16 lo = __float2bfloat16(v - __bfloat162float(h));
    g_wimg_all[l][n * 72 + k]            = __bfloat16_as_ushort(h);
    g_wimg_all[l][320 * 72 + n * 72 + k] = __bfloat16_as_ushort(lo);
}

// =====================================================================
// CSR build: zero -> hist -> scan(3 phase) -> scatter
// bins: big dst d at [d], small dst d at [NNODE+1+d].
// =====================================================================
__global__ __launch_bounds__(1024) void csr_zero()
{
    int i = blockIdx.x * 1024 + threadIdx.x;
    if (i < NBINS) g_rowptr[i] = 0;
}

__global__ __launch_bounds__(256) void csr_hist(
    const int* __restrict__ dstB, const int* __restrict__ dstS, int E, int SE)
{
    int i = blockIdx.x * 256 + threadIdx.x;
    if (i < E) {
        atomicAdd(&g_rowptr[__ldg(&dstB[i])], 1);
    } else if (i < E + SE) {
        atomicAdd(&g_rowptr[NNODE + 1 + __ldg(&dstS[i - E])], 1);
    }
}

__global__ __launch_bounds__(1024) void csr_scan1()
{
    __shared__ int s[1024];
    int tid = threadIdx.x;
    int gid = blockIdx.x * 1024 + tid;
    int v = (gid < NBINS) ? g_rowptr[gid] : 0;
    s[tid] = v;
    __syncthreads();
#pragma unroll
    for (int off = 1; off < 1024; off <<= 1) {
        int t = (tid >= off) ? s[tid - off] : 0;
        __syncthreads();
        s[tid] += t;
        __syncthreads();
    }
    if (gid < NBINS) g_rowptr[gid] = s[tid] - v;     // exclusive within block
    if (tid == 1023) g_blocksum[blockIdx.x] = s[1023];
}

__global__ void csr_scan2()
{
    if (threadIdx.x == 0 && blockIdx.x == 0) {
        int run = 0;
        for (int b = 0; b < NSCANB; b++) {
            int t = g_blocksum[b];
            g_blocksum[b] = run;
            run += t;
        }
    }
}

__global__ __launch_bounds__(1024) void csr_scan3()
{
    int gid = blockIdx.x * 1024 + threadIdx.x;
    if (gid < NBINS) {
        int v = g_rowptr[gid] + g_blocksum[gid >> 10];
        g_rowptr[gid] = v;
        g_cursor[gid] = v;
    }
}

__global__ __launch_bounds__(256) void csr_scatter(
    const int* __restrict__ srcB, const int* __restrict__ dstB,
    const int* __restrict__ etB,
    const int* __restrict__ srcS, const int* __restrict__ dstS,
    const int* __restrict__ etS, int E, int SE)
{
    int i = blockIdx.x * 256 + threadIdx.x;
    if (i < E) {
        int d = __ldg(&dstB[i]);
        unsigned pk = (unsigned)__ldg(&srcB[i]) | ((unsigned)__ldg(&etB[i]) << 20);
        int pos = atomicAdd(&g_cursor[d], 1);
        g_epack[pos] = pk;
    } else if (i < E + SE) {
        int k = i - E;
        int d = __ldg(&dstS[k]);
        unsigned pk = (unsigned)__ldg(&srcS[k]) | ((unsigned)__ldg(&etS[k]) << 20);
        int pos = atomicAdd(&g_cursor[NNODE + 1 + d], 1);
        g_epack[pos] = pk;
    }
}

// =====================================================================
// tc_dense: 256-row tile, 512 threads (16 warps x 16 rows).
// y = x @ [basis0..3 | root] via mma.sync bf16 3-term split, fp32 accum.
// Epilogue: xw_r = sum_b comp[r,b]*y_b -> g_xwh (fp16, streaming);
//           g_agg = y_root + bias (fp32).
// =====================================================================
__global__ __launch_bounds__(512, 1) void tc_dense(
    const float* __restrict__ xin,   // nullptr -> g_cs slice
    int layer,
    const float* __restrict__ comp,  // [8][4]
    const float* __restrict__ bias)  // [64]
{
    extern __shared__ char sm[];
    int tid = threadIdx.x;

    // ---- copy W image (92160 B = 5760 uint4) ----
    {
        const uint4* wi = reinterpret_cast<const uint4*>(g_wimg_all[layer]);
#pragma unroll
        for (int i = 0; i < 12; i++) {
            int idx = tid + 512 * i;
            if (idx < 5760)
                *reinterpret_cast<uint4*>(sm + SM_WHI + idx * 16) = wi[idx];
        }
    }
    if (tid < 32) reinterpret_cast<float*>(sm + SM_COMP)[tid] = comp[tid];
    if (tid >= 64 && tid < 128)
        reinterpret_cast<float*>(sm + SM_BIASO)[tid - 64] = bias[tid - 64];

    // ---- stage x tile as bf16 hi/lo, stride 72 halfs ----
    const float* xp;
    int xstride;
    if (xin != nullptr) { xp = xin; xstride = 64; }
    else               { xp = g_cs + (layer - 1) * 64; xstride = TDIM; }

    {
        int row  = tid >> 1;
        int half = tid & 1;
        int grow = blockIdx.x * 256 + row;
        const float* xr = xp + (size_t)grow * xstride + half * 32;
        char* xh = sm + SM_XHI + row * 144 + half * 64;
        char* xl = sm + SM_XLO + row * 144 + half * 64;
#pragma unroll
        for (int q = 0; q < 8; q++) {
            float4 v = make_float4(0.f, 0.f, 0.f, 0.f);
            if (grow < NNODE) v = *reinterpret_cast<const float4*>(xr + q * 4);
            __nv_bfloat16 h0 = __float2bfloat16(v.x), h1 = __float2bfloat16(v.y);
            __nv_bfloat16 h2 = __float2bfloat16(v.z), h3 = __float2bfloat16(v.w);
            uint2 hp;
            hp.x = (uint32_t)__bfloat16_as_ushort(h0) | ((uint32_t)__bfloat16_as_ushort(h1) << 16);
            hp.y = (uint32_t)__bfloat16_as_ushort(h2) | ((uint32_t)__bfloat16_as_ushort(h3) << 16);
            __nv_bfloat16 l0 = __float2bfloat16(v.x - __bfloat162float(h0));
            __nv_bfloat16 l1 = __float2bfloat16(v.y - __bfloat162float(h1));
            __nv_bfloat16 l2 = __float2bfloat16(v.z - __bfloat162float(h2));
            __nv_bfloat16 l3 = __float2bfloat16(v.w - __bfloat162float(h3));
            uint2 lp;
            lp.x = (uint32_t)__bfloat16_as_ushort(l0) | ((uint32_t)__bfloat16_as_ushort(l1) << 16);
            lp.y = (uint32_t)__bfloat16_as_ushort(l2) | ((uint32_t)__bfloat16_as_ushort(l3) << 16);
            *reinterpret_cast<uint2*>(xh + q * 8) = hp;
            *reinterpret_cast<uint2*>(xl + q * 8) = lp;
        }
    }
    __syncthreads();

    // ---- per-warp MMA: 16 rows x 320 cols ----
    int lane = tid & 31, wid = tid >> 5;
    int g = lane >> 2, j = lane & 3;
    int lr = wid * 16 + g;
    int grow0 = blockIdx.x * 256 + lr;

    uint32_t Ah[4][4], Al[4][4];
#pragma unroll
    for (int ks = 0; ks < 4; ks++) {
        int c2 = (ks * 16 + 2 * j) * 2;
        Ah[ks][0] = *reinterpret_cast<const uint32_t*>(sm + SM_XHI + lr * 144 + c2);
        Ah[ks][1] = *reinterpret_cast<const uint32_t*>(sm + SM_XHI + (lr + 8) * 144 + c2);
        Ah[ks][2] = *reinterpret_cast<const uint32_t*>(sm + SM_XHI + lr * 144 + c2 + 16);
        Ah[ks][3] = *reinterpret_cast<const uint32_t*>(sm + SM_XHI + (lr + 8) * 144 + c2 + 16);
        Al[ks][0] = *reinterpret_cast<const uint32_t*>(sm + SM_XLO + lr * 144 + c2);
        Al[ks][1] = *reinterpret_cast<const uint32_t*>(sm + SM_XLO + (lr + 8) * 144 + c2);
        Al[ks][2] = *reinterpret_cast<const uint32_t*>(sm + SM_XLO + lr * 144 + c2 + 16);
        Al[ks][3] = *reinterpret_cast<const uint32_t*>(sm + SM_XLO + (lr + 8) * 144 + c2 + 16);
    }

#pragma unroll
    for (int eg = 0; eg < 8; eg++) {
        float acc[4][4];
#pragma unroll
        for (int bt = 0; bt < 4; bt++)
#pragma unroll
            for (int q = 0; q < 4; q++) acc[bt][q] = 0.f;

#pragma unroll
        for (int ks = 0; ks < 4; ks++) {
            int kb2 = (ks * 16 + 2 * j) * 2;
            uint32_t Bh[4][2], Bl[4][2];
#pragma unroll
            for (int bt = 0; bt < 4; bt++) {
                int n = bt * 64 + eg * 8 + g;
                const char* wh = sm + SM_WHI + n * 144 + kb2;
                const char* wl = sm + SM_WLO + n * 144 + kb2;
                Bh[bt][0] = *reinterpret_cast<const uint32_t*>(wh);
                Bh[bt][1] = *reinterpret_cast<const uint32_t*>(wh + 16);
                Bl[bt][0] = *reinterpret_cast<const uint32_t*>(wl);
                Bl[bt][1] = *reinterpret_cast<const uint32_t*>(wl + 16);
            }
#pragma unroll
            for (int bt = 0; bt < 4; bt++) MMA_BF16(acc[bt], Ah[ks], Bh[bt][0], Bh[bt][1]);
#pragma unroll
            for (int bt = 0; bt < 4; bt++) MMA_BF16(acc[bt], Ah[ks], Bl[bt][0], Bl[bt][1]);
#pragma unroll
            for (int bt = 0; bt < 4; bt++) MMA_BF16(acc[bt], Al[ks], Bh[bt][0], Bh[bt][1]);
        }

        unsigned long long p0[4], p1[4];
#pragma unroll
        for (int bt = 0; bt < 4; bt++) {
            p0[bt] = pack_f32x2(acc[bt][0], acc[bt][1]);
            p1[bt] = pack_f32x2(acc[bt][2], acc[bt][3]);
        }
        int e = eg * 8 + 2 * j;
#pragma unroll
        for (int rel = 0; rel < 8; rel++) {
            float4 c4 = *reinterpret_cast<const float4*>(sm + SM_COMP + rel * 16);
            unsigned long long s0 = 0ull, s1 = 0ull;
            ffma2(s0, dup_f32x2(c4.x), p0[0]); ffma2(s1, dup_f32x2(c4.x), p1[0]);
            ffma2(s0, dup_f32x2(c4.y), p0[1]); ffma2(s1, dup_f32x2(c4.y), p1[1]);
            ffma2(s0, dup_f32x2(c4.z), p0[2]); ffma2(s1, dup_f32x2(c4.z), p1[2]);
            ffma2(s0, dup_f32x2(c4.w), p0[3]); ffma2(s1, dup_f32x2(c4.w), p1[3]);
            float2 f0 = *reinterpret_cast<float2*>(&s0);
            float2 f1 = *reinterpret_cast<float2*>(&s1);
            if (grow0 < NNODE) {
                __half2 h = __floats2half2_rn(f0.x, f0.y);
                __stcs(reinterpret_cast<__half2*>(
                           g_xwh + (size_t)grow0 * 512 + rel * 64 + e), h);
            }
            if (grow0 + 8 < NNODE) {
                __half2 h = __floats2half2_rn(f1.x, f1.y);
                __stcs(reinterpret_cast<__half2*>(
                           g_xwh + (size_t)(grow0 + 8) * 512 + rel * 64 + e), h);
            }
        }
    }

    // ---- root columns -> g_agg (+bias) ----
    const float* sb = reinterpret_cast<const float*>(sm + SM_BIASO);
#pragma unroll
    for (int nt = 0; nt < 8; nt++) {
        float acc[4] = {0.f, 0.f, 0.f, 0.f};
#pragma unroll
        for (int ks = 0; ks < 4; ks++) {
            int kb2 = (ks * 16 + 2 * j) * 2;
            int n = 256 + nt * 8 + g;
            const char* wh = sm + SM_WHI + n * 144 + kb2;
            const char* wl = sm + SM_WLO + n * 144 + kb2;
            uint32_t bh0 = *reinterpret_cast<const uint32_t*>(wh);
            uint32_t bh1 = *reinterpret_cast<const uint32_t*>(wh + 16);
            uint32_t bl0 = *reinterpret_cast<const uint32_t*>(wl);
            uint32_t bl1 = *reinterpret_cast<const uint32_t*>(wl + 16);
            MMA_BF16(acc, Ah[ks], bh0, bh1);
            MMA_BF16(acc, Ah[ks], bl0, bl1);
            MMA_BF16(acc, Al[ks], bh0, bh1);
        }
        int e = nt * 8 + 2 * j;
        float b0 = sb[e], b1 = sb[e + 1];
        if (grow0 < NNODE) {
            float2 v = make_float2(acc[0] + b0, acc[1] + b1);
            *reinterpret_cast<float2*>(g_agg + (size_t)grow0 * 64 + e) = v;
        }
        if (grow0 + 8 < NNODE) {
            float2 v = make_float2(acc[2] + b0, acc[3] + b1);
            *reinterpret_cast<float2*>(g_agg + (size_t)(grow0 + 8) * 64 + e) = v;
        }
    }
}

// =====================================================================
// edge_csr: 16 lanes per dst node. acc = g_agg[d] (root+bias), then
// gather+sum fp16 xw[src][et] (128B row, one line) over incoming edges,
// tanh, write straight into g_cs. No atomics, no finish kernel.
// =====================================================================
__device__ __forceinline__ float4 xw_row(unsigned pk, int j) {
    uint2 u = __ldcs(reinterpret_cast<const uint2*>(
        g_xwh + (size_t)(pk & 0xFFFFFu) * 512 + ((pk >> 20) & 7u) * 64 + j * 4));
    __half2 h0 = *reinterpret_cast<__half2*>(&u.x);
    __half2 h1 = *reinterpret_cast<__half2*>(&u.y);
    float2 f0 = __half22float2(h0);
    float2 f1 = __half22float2(h1);
    return make_float4(f0.x, f0.y, f1.x, f1.y);
}

__global__ __launch_bounds__(256) void edge_csr(int rbase, int loff)
{
    int grp = blockIdx.x * 16 + (threadIdx.x >> 4);
    if (grp >= NNODE) return;
    int j = threadIdx.x & 15;

    int beg = __ldg(&g_rowptr[rbase + grp]);
    int end = __ldg(&g_rowptr[rbase + grp + 1]);

    float4 acc = *reinterpret_cast<const float4*>(g_agg + (size_t)grp * 64 + j * 4);

    int e = beg;
    for (; e + 4 <= end; e += 4) {
        unsigned p0 = __ldg(&g_epack[e]);
        unsigned p1 = __ldg(&g_epack[e + 1]);
        unsigned p2 = __ldg(&g_epack[e + 2]);
        unsigned p3 = __ldg(&g_epack[e + 3]);
        float4 v0 = xw_row(p0, j);
        float4 v1 = xw_row(p1, j);
        float4 v2 = xw_row(p2, j);
        float4 v3 = xw_row(p3, j);
        acc.x += (v0.x + v1.x) + (v2.x + v3.x);
        acc.y += (v0.y + v1.y) + (v2.y + v3.y);
        acc.z += (v0.z + v1.z) + (v2.z + v3.z);
        acc.w += (v0.w + v1.w) + (v2.w + v3.w);
    }
    for (; e < end; ++e) {
        float4 v = xw_row(__ldg(&g_epack[e]), j);
        acc.x += v.x; acc.y += v.y; acc.z += v.z; acc.w += v.w;
    }

    acc.x = tanhf(acc.x); acc.y = tanhf(acc.y);
    acc.z = tanhf(acc.z); acc.w = tanhf(acc.w);
    *reinterpret_cast<float4*>(g_cs + (size_t)grp * TDIM + loff + j * 4) = acc;
}

// =====================================================================
// Tail A: gather item_embs_conv + user_emb outputs, build sequence sums.
// =====================================================================
__global__ __launch_bounds__(TDIM) void tail_a(
    const int* __restrict__ users,
    const int* __restrict__ seqs,
    float* __restrict__ out_user,
    float* __restrict__ out_item)
{
    int b = blockIdx.x;
    int t = threadIdx.x;
    float s = 0.f;
#pragma unroll
    for (int j = 0; j < SEQ; j++) {
        int node = __ldg(&seqs[b * SEQ + j]);
        float v  = __ldg(&g_cs[(size_t)node * TDIM + t]);
        out_item[((size_t)b * SEQ + j) * TDIM + t] = v;
        s += v;
    }
    g_ssum[b * TDIM + t] = s;
    int u = __ldg(&users[b]);
    out_user[b * TDIM + t] = __ldg(&g_cs[(size_t)u * TDIM + t]);
}

// =====================================================================
// tb_uv: uv = user_emb + ssum @ WV.  8 batches per block.
// (attention collapses: softmax over query axis => column sums == 1)
// =====================================================================
__global__ __launch_bounds__(TDIM) void tb_uv(
    const float* __restrict__ WV,
    const float* __restrict__ user_emb)
{
    __shared__ float ss[8 * TDIM];
    int b0 = blockIdx.x * 8;
    int t  = threadIdx.x;

#pragma unroll
    for (int i = 0; i < 8; i++)
        ss[i * TDIM + t] = g_ssum[(b0 + i) * TDIM + t];
    __syncthreads();

    float acc[8];
#pragma unroll
    for (int i = 0; i < 8; i++) acc[i] = 0.f;

#pragma unroll 4
    for (int k = 0; k < TDIM; ++k) {
        float w = __ldg(&WV[k * TDIM + t]);
#pragma unroll
        for (int i = 0; i < 8; i++) acc[i] = fmaf(ss[i * TDIM + k], w, acc[i]);
    }
#pragma unroll
    for (int i = 0; i < 8; i++)
        g_uv[(b0 + i) * TDIM + t] = acc[i] + user_emb[(b0 + i) * TDIM + t];
}

// =====================================================================
// tb_res: res[b,k] = pe_w[item]·uv[b] + pe_b[item]
// =====================================================================
__global__ __launch_bounds__(TDIM) void tb_res(
    const float* __restrict__ predict_w,
    const float* __restrict__ predict_b,
    const int*   __restrict__ items,
    float* __restrict__ res)
{
    __shared__ float uv[TDIM];
    int b = blockIdx.x;
    int t = threadIdx.x;
    uv[t] = g_uv[b * TDIM + t];
    __syncthreads();

    int w    = t >> 5;
    int lane = t & 31;
    for (int k = w; k < NPRED; k += TDIM / 32) {
        int it = __ldg(&items[b * NPRED + k]);
        const float* pw = predict_w + (size_t)it * TDIM;
        float s = 0.f;
#pragma unroll
        for (int c = lane; c < TDIM; c += 32) s += __ldg(&pw[c]) * uv[c];
#pragma unroll
        for (int off = 16; off > 0; off >>= 1)
            s += __shfl_down_sync(0xffffffffu, s, off);
        if (lane == 0)
            res[b * NPRED + k] = s + __ldg(&predict_b[it]);
    }
}

// =====================================================================
// Launch
// =====================================================================
extern "C" void kernel_launch(void* const* d_in, const int* in_sizes, int n_in,
                              void* d_out, int out_size)
{
    const float* node_emb  = (const float*)d_in[0];
    const float* predict_w = (const float*)d_in[1];
    const float* predict_b = (const float*)d_in[2];
    const float* basis     = (const float*)d_in[3];
    const float* comp      = (const float*)d_in[4];
    const float* root      = (const float*)d_in[5];
    const float* bias      = (const float*)d_in[6];
    const float* sbasis    = (const float*)d_in[7];
    const float* scomp     = (const float*)d_in[8];
    const float* sroot     = (const float*)d_in[9];
    const float* sbias     = (const float*)d_in[10];
    // d_in[11] = WQ, d_in[12] = WK : provably unused (softmax over query axis)
    const float* WV        = (const float*)d_in[13];
    const int* batch_users = (const int*)d_in[14];
    const int* batch_seq   = (const int*)d_in[15];
    const int* items       = (const int*)d_in[16];
    const int* edge_index  = (const int*)d_in[17];
    const int* edge_type   = (const int*)d_in[18];
    // d_in[19] = node_no (identity gather, unused)
    const int* sedge_index = (const int*)d_in[20];
    const int* sedge_type  = (const int*)d_in[21];

    const int E  = in_sizes[18];   // 1,000,000
    const int SE = in_sizes[21];   //   200,000

    const int* srcB = edge_index;
    const int* dstB = edge_index + E;
    const int* srcS = sedge_index;
    const int* dstS = sedge_index + SE;

    float* out_res  = (float*)d_out;                       // [1024][20]
    float* out_user = out_res + BATCH * NPRED;             // [1024][384]
    float* out_item = out_user + BATCH * TDIM;             // [1024][20][384]

    cudaFuncSetAttribute(tc_dense,
                         cudaFuncAttributeMaxDynamicSharedMemorySize, TC_SMEM);

    // ---- one-time prep: W images + CSR for both graphs ----
    w_prep_all<<<480, 256>>>(basis, root, sbasis, sroot);
    csr_zero<<<NSCANB, 1024>>>();
    csr_hist<<<(E + SE + 255) / 256, 256>>>(dstB, dstS, E, SE);
    csr_scan1<<<NSCANB, 1024>>>();
    csr_scan2<<<1, 32>>>();
    csr_scan3<<<NSCANB, 1024>>>();
    csr_scatter<<<(E + SE + 255) / 256, 256>>>(srcB, dstB, edge_type,
                                               srcS, dstS, sedge_type, E, SE);

    const int tc_grid  = (NNODE + 255) / 256;              // 586
    const int csr_grid = (NNODE + 15) / 16;                // 9375

    for (int l = 0; l < 6; ++l) {
        bool big = (l < 3);
        int  ll  = big ? l : l - 3;
        const float* Bi = (big ? bias : sbias) + ll * 64;
        const float* C  = (big ? comp : scomp) + ll * 32;
        const float* xi = (l == 0) ? node_emb : nullptr;
        int rbase       = big ? 0 : (NNODE + 1);

        tc_dense<<<tc_grid, 512, TC_SMEM>>>(xi, l, C, Bi);
        edge_csr<<<csr_grid, 256>>>(rbase, l * 64);
    }

    tail_a<<<BATCH, TDIM>>>(batch_users, batch_seq, out_user, out_item);
    tb_uv<<<BATCH / 8, TDIM>>>(WV, out_user);
    tb_res<<<BATCH, TDIM>>>(predict_w, predict_b, items, out_res);
}

// round 17
// speedup vs baseline: 1.5744x; 1.5744x over previous
#include <cuda_runtime.h>
#include <cuda_bf16.h>
#include <cstdint>
#include <cstddef>

// ---------------- problem constants ----------------
#define NNODE  150000
#define N64    (NNODE * 64)          // 9,600,000
#define TDIM   384
#define BATCH  1024
#define SEQ    20
#define NPRED  20
#define EMAX   1000000
#define SEMAX  200000
#define NBINS  (2 * NNODE + 2)       // big rowptr [0..N], small [N+1..2N+1]
#define NSCANB ((NBINS + 1023) / 1024)

// ---------------- scratch (device globals) ----------------
__device__ float g_xw[8ull * N64];           // xw_r = x @ W_r   [N][8][64]  (307 MB)
__device__ float g_agg[N64];                 // root + bias      [N][64]
__device__ float g_cs[(size_t)NNODE * TDIM]; // concat of 6 states [N][384]
__device__ float g_ssum[BATCH * TDIM];
__device__ float g_uv[BATCH * TDIM];
// all 6 layers' bf16 W images: per layer [hi 320x72][lo 320x72] halfs
__device__ unsigned short g_wimg_all[6][2 * 320 * 72];
// CSR structures (both graphs share one packed edge array)
__device__ int g_rowptr[NBINS];
__device__ int g_cursor[NBINS];
__device__ int g_blocksum[NSCANB + 1];
__device__ unsigned int g_epack[EMAX + SEMAX];
// per-graph relation-usage mask: bit r of g_rmask[g][n] = node n is src of rel r
__device__ unsigned int g_rmask[2][NNODE];

// ---------------- helpers ----------------
__device__ __forceinline__ unsigned long long dup_f32x2(float v) {
    unsigned long long a;
    asm("mov.b64 %0, {%1, %1};" : "=l"(a) : "f"(v));
    return a;
}
__device__ __forceinline__ unsigned long long pack_f32x2(float x, float y) {
    unsigned long long a;
    asm("mov.b64 %0, {%1, %2};" : "=l"(a) : "f"(x), "f"(y));
    return a;
}
__device__ __forceinline__ void ffma2(unsigned long long& acc,
                                      unsigned long long a, unsigned long long b) {
    asm("fma.rn.f32x2 %0, %1, %2, %0;" : "+l"(acc) : "l"(a), "l"(b));
}

// mma.sync m16n8k16 bf16 (baseline PTX, works on compute_103)
#define MMA_BF16(d, a, b0_, b1_) \
    asm volatile("mma.sync.aligned.m16n8k16.row.col.f32.bf16.bf16.f32 " \
        "{%0,%1,%2,%3}, {%4,%5,%6,%7}, {%8,%9}, {%0,%1,%2,%3};" \
        : "+f"((d)[0]), "+f"((d)[1]), "+f"((d)[2]), "+f"((d)[3]) \
        : "r"((a)[0]), "r"((a)[1]), "r"((a)[2]), "r"((a)[3]), \
          "r"(b0_), "r"(b1_))

// smem byte offsets for tc_dense (stride 144B per row everywhere)
#define SM_XHI   0
#define SM_XLO   (256 * 144)             // 36864
#define SM_WHI   (2 * 256 * 144)         // 73728
#define SM_WLO   (SM_WHI + 320 * 144)    // 119808
#define SM_COMP  (SM_WLO + 320 * 144)    // 165888
#define SM_BIASO (SM_COMP + 128)         // 166016
#define TC_SMEM  (SM_BIASO + 256)        // 166272

// =====================================================================
// w_prep_all: bake all 6 layers' W = [basis0..3 | root] bf16 hi/lo
// images, layout [n][k] stride 72 halfs.
// =====================================================================
__global__ __launch_bounds__(256) void w_prep_all(
    const float* __restrict__ basis, const float* __restrict__ root,
    const float* __restrict__ sbasis, const float* __restrict__ sroot)
{
    int idx = blockIdx.x * 256 + threadIdx.x;      // 0..122879
    if (idx >= 6 * 320 * 64) return;
    int l   = idx / (320 * 64);
    int rem = idx - l * (320 * 64);
    int n = rem >> 6;
    int k = rem & 63;
    const float* B = (l < 3) ? basis + l * 16384 : sbasis + (l - 3) * 16384;
    const float* R = (l < 3) ? root + l * 4096  : sroot + (l - 3) * 4096;
    float v = (n < 256) ? B[(n >> 6) * 4096 + k * 64 + (n & 63)]
                        : R[k * 64 + (n - 256)];
    __nv_bfloat16 h = __float2bfloat16(v);
    __nv_bfloat16 lo = __float2bfloat16(v - __bfloat162float(h));
    g_wimg_all[l][n * 72 + k]            = __bfloat16_as_ushort(h);
    g_wimg_all[l][320 * 72 + n * 72 + k] = __bfloat16_as_ushort(lo);
}

// =====================================================================
// relation-usage masks
// =====================================================================
__global__ __launch_bounds__(1024) void rmask_zero()
{
    int i = blockIdx.x * 1024 + threadIdx.x;
    if (i < 2 * NNODE) (&g_rmask[0][0])[i] = 0u;
}

__global__ __launch_bounds__(256) void rmask_build(
    const int* __restrict__ srcB, const int* __restrict__ etB,
    const int* __restrict__ srcS, const int* __restrict__ etS, int E, int SE)
{
    int i = blockIdx.x * 256 + threadIdx.x;
    if (i < E) {
        atomicOr(&g_rmask[0][__ldg(&srcB[i])], 1u << __ldg(&etB[i]));
    } else if (i < E + SE) {
        int k = i - E;
        atomicOr(&g_rmask[1][__ldg(&srcS[k])], 1u << __ldg(&etS[k]));
    }
}

// =====================================================================
// CSR build: zero -> hist -> scan(3 phase) -> scatter
// bins: big dst d at [d], small dst d at [NNODE+1+d].
// =====================================================================
__global__ __launch_bounds__(1024) void csr_zero()
{
    int i = blockIdx.x * 1024 + threadIdx.x;
    if (i < NBINS) g_rowptr[i] = 0;
}

__global__ __launch_bounds__(256) void csr_hist(
    const int* __restrict__ dstB, const int* __restrict__ dstS, int E, int SE)
{
    int i = blockIdx.x * 256 + threadIdx.x;
    if (i < E) {
        atomicAdd(&g_rowptr[__ldg(&dstB[i])], 1);
    } else if (i < E + SE) {
        atomicAdd(&g_rowptr[NNODE + 1 + __ldg(&dstS[i - E])], 1);
    }
}

__global__ __launch_bounds__(1024) void csr_scan1()
{
    __shared__ int s[1024];
    int tid = threadIdx.x;
    int gid = blockIdx.x * 1024 + tid;
    int v = (gid < NBINS) ? g_rowptr[gid] : 0;
    s[tid] = v;
    __syncthreads();
#pragma unroll
    for (int off = 1; off < 1024; off <<= 1) {
        int t = (tid >= off) ? s[tid - off] : 0;
        __syncthreads();
        s[tid] += t;
        __syncthreads();
    }
    if (gid < NBINS) g_rowptr[gid] = s[tid] - v;     // exclusive within block
    if (tid == 1023) g_blocksum[blockIdx.x] = s[1023];
}

__global__ void csr_scan2()
{
    if (threadIdx.x == 0 && blockIdx.x == 0) {
        int run = 0;
        for (int b = 0; b < NSCANB; b++) {
            int t = g_blocksum[b];
            g_blocksum[b] = run;
            run += t;
        }
    }
}

__global__ __launch_bounds__(1024) void csr_scan3()
{
    int gid = blockIdx.x * 1024 + threadIdx.x;
    if (gid < NBINS) {
        int v = g_rowptr[gid] + g_blocksum[gid >> 10];
        g_rowptr[gid] = v;
        g_cursor[gid] = v;
    }
}

__global__ __launch_bounds__(256) void csr_scatter(
    const int* __restrict__ srcB, const int* __restrict__ dstB,
    const int* __restrict__ etB,
    const int* __restrict__ srcS, const int* __restrict__ dstS,
    const int* __restrict__ etS, int E, int SE)
{
    int i = blockIdx.x * 256 + threadIdx.x;
    if (i < E) {
        int d = __ldg(&dstB[i]);
        unsigned pk = (unsigned)__ldg(&srcB[i]) | ((unsigned)__ldg(&etB[i]) << 20);
        int pos = atomicAdd(&g_cursor[d], 1);
        g_epack[pos] = pk;
    } else if (i < E + SE) {
        int k = i - E;
        int d = __ldg(&dstS[k]);
        unsigned pk = (unsigned)__ldg(&srcS[k]) | ((unsigned)__ldg(&etS[k]) << 20);
        int pos = atomicAdd(&g_cursor[NNODE + 1 + d], 1);
        g_epack[pos] = pk;
    }
}

// =====================================================================
// tc_dense: 256-row tile, 512 threads (16 warps x 16 rows).
// y = x @ [basis0..3 | root] via mma.sync bf16 3-term split, fp32 accum.
// Epilogue: xw_r = sum_b comp[r,b]*y_b -> g_xw, stored ONLY for (n,r)
// slots this graph actually gathers (g_rmask); g_agg = y_root + bias.
// =====================================================================
__global__ __launch_bounds__(512, 1) void tc_dense(
    const float* __restrict__ xin,   // nullptr -> g_cs slice
    int layer,
    int gsel,                        // 0 = big graph mask, 1 = small
    const float* __restrict__ comp,  // [8][4]
    const float* __restrict__ bias)  // [64]
{
    extern __shared__ char sm[];
    int tid = threadIdx.x;

    // ---- copy W image (92160 B = 5760 uint4) ----
    {
        const uint4* wi = reinterpret_cast<const uint4*>(g_wimg_all[layer]);
#pragma unroll
        for (int i = 0; i < 12; i++) {
            int idx = tid + 512 * i;
            if (idx < 5760)
                *reinterpret_cast<uint4*>(sm + SM_WHI + idx * 16) = wi[idx];
        }
    }
    if (tid < 32) reinterpret_cast<float*>(sm + SM_COMP)[tid] = comp[tid];
    if (tid >= 64 && tid < 128)
        reinterpret_cast<float*>(sm + SM_BIASO)[tid - 64] = bias[tid - 64];

    // ---- stage x tile as bf16 hi/lo, stride 72 halfs ----
    const float* xp;
    int xstride;
    if (xin != nullptr) { xp = xin; xstride = 64; }
    else               { xp = g_cs + (layer - 1) * 64; xstride = TDIM; }

    {
        int row  = tid >> 1;
        int half = tid & 1;
        int grow = blockIdx.x * 256 + row;
        const float* xr = xp + (size_t)grow * xstride + half * 32;
        char* xh = sm + SM_XHI + row * 144 + half * 64;
        char* xl = sm + SM_XLO + row * 144 + half * 64;
#pragma unroll
        for (int q = 0; q < 8; q++) {
            float4 v = make_float4(0.f, 0.f, 0.f, 0.f);
            if (grow < NNODE) v = *reinterpret_cast<const float4*>(xr + q * 4);
            __nv_bfloat16 h0 = __float2bfloat16(v.x), h1 = __float2bfloat16(v.y);
            __nv_bfloat16 h2 = __float2bfloat16(v.z), h3 = __float2bfloat16(v.w);
            uint2 hp;
            hp.x = (uint32_t)__bfloat16_as_ushort(h0) | ((uint32_t)__bfloat16_as_ushort(h1) << 16);
            hp.y = (uint32_t)__bfloat16_as_ushort(h2) | ((uint32_t)__bfloat16_as_ushort(h3) << 16);
            __nv_bfloat16 l0 = __float2bfloat16(v.x - __bfloat162float(h0));
            __nv_bfloat16 l1 = __float2bfloat16(v.y - __bfloat162float(h1));
            __nv_bfloat16 l2 = __float2bfloat16(v.z - __bfloat162float(h2));
            __nv_bfloat16 l3 = __float2bfloat16(v.w - __bfloat162float(h3));
            uint2 lp;
            lp.x = (uint32_t)__bfloat16_as_ushort(l0) | ((uint32_t)__bfloat16_as_ushort(l1) << 16);
            lp.y = (uint32_t)__bfloat16_as_ushort(l2) | ((uint32_t)__bfloat16_as_ushort(l3) << 16);
            *reinterpret_cast<uint2*>(xh + q * 8) = hp;
            *reinterpret_cast<uint2*>(xl + q * 8) = lp;
        }
    }
    __syncthreads();

    // ---- per-warp MMA: 16 rows x 320 cols ----
    int lane = tid & 31, wid = tid >> 5;
    int g = lane >> 2, j = lane & 3;
    int lr = wid * 16 + g;
    int grow0 = blockIdx.x * 256 + lr;

    unsigned m0 = 0u, m1 = 0u;
    if (grow0 < NNODE)     m0 = __ldg(&g_rmask[gsel][grow0]);
    if (grow0 + 8 < NNODE) m1 = __ldg(&g_rmask[gsel][grow0 + 8]);

    uint32_t Ah[4][4], Al[4][4];
#pragma unroll
    for (int ks = 0; ks < 4; ks++) {
        int c2 = (ks * 16 + 2 * j) * 2;
        Ah[ks][0] = *reinterpret_cast<const uint32_t*>(sm + SM_XHI + lr * 144 + c2);
        Ah[ks][1] = *reinterpret_cast<const uint32_t*>(sm + SM_XHI + (lr + 8) * 144 + c2);
        Ah[ks][2] = *reinterpret_cast<const uint32_t*>(sm + SM_XHI + lr * 144 + c2 + 16);
        Ah[ks][3] = *reinterpret_cast<const uint32_t*>(sm + SM_XHI + (lr + 8) * 144 + c2 + 16);
        Al[ks][0] = *reinterpret_cast<const uint32_t*>(sm + SM_XLO + lr * 144 + c2);
        Al[ks][1] = *reinterpret_cast<const uint32_t*>(sm + SM_XLO + (lr + 8) * 144 + c2);
        Al[ks][2] = *reinterpret_cast<const uint32_t*>(sm + SM_XLO + lr * 144 + c2 + 16);
        Al[ks][3] = *reinterpret_cast<const uint32_t*>(sm + SM_XLO + (lr + 8) * 144 + c2 + 16);
    }

#pragma unroll
    for (int eg = 0; eg < 8; eg++) {
        float acc[4][4];
#pragma unroll
        for (int bt = 0; bt < 4; bt++)
#pragma unroll
            for (int q = 0; q < 4; q++) acc[bt][q] = 0.f;

#pragma unroll
        for (int ks = 0; ks < 4; ks++) {
            int kb2 = (ks * 16 + 2 * j) * 2;
            uint32_t Bh[4][2], Bl[4][2];
#pragma unroll
            for (int bt = 0; bt < 4; bt++) {
                int n = bt * 64 + eg * 8 + g;
                const char* wh = sm + SM_WHI + n * 144 + kb2;
                const char* wl = sm + SM_WLO + n * 144 + kb2;
                Bh[bt][0] = *reinterpret_cast<const uint32_t*>(wh);
                Bh[bt][1] = *reinterpret_cast<const uint32_t*>(wh + 16);
                Bl[bt][0] = *reinterpret_cast<const uint32_t*>(wl);
                Bl[bt][1] = *reinterpret_cast<const uint32_t*>(wl + 16);
            }
#pragma unroll
            for (int bt = 0; bt < 4; bt++) MMA_BF16(acc[bt], Ah[ks], Bh[bt][0], Bh[bt][1]);
#pragma unroll
            for (int bt = 0; bt < 4; bt++) MMA_BF16(acc[bt], Ah[ks], Bl[bt][0], Bl[bt][1]);
#pragma unroll
            for (int bt = 0; bt < 4; bt++) MMA_BF16(acc[bt], Al[ks], Bh[bt][0], Bh[bt][1]);
        }

        unsigned long long p0[4], p1[4];
#pragma unroll
        for (int bt = 0; bt < 4; bt++) {
            p0[bt] = pack_f32x2(acc[bt][0], acc[bt][1]);
            p1[bt] = pack_f32x2(acc[bt][2], acc[bt][3]);
        }
        int e = eg * 8 + 2 * j;
#pragma unroll
        for (int rel = 0; rel < 8; rel++) {
            float4 c4 = *reinterpret_cast<const float4*>(sm + SM_COMP + rel * 16);
            unsigned long long s0 = 0ull, s1 = 0ull;
            ffma2(s0, dup_f32x2(c4.x), p0[0]); ffma2(s1, dup_f32x2(c4.x), p1[0]);
            ffma2(s0, dup_f32x2(c4.y), p0[1]); ffma2(s1, dup_f32x2(c4.y), p1[1]);
            ffma2(s0, dup_f32x2(c4.z), p0[2]); ffma2(s1, dup_f32x2(c4.z), p1[2]);
            ffma2(s0, dup_f32x2(c4.w), p0[3]); ffma2(s1, dup_f32x2(c4.w), p1[3]);
            if ((m0 >> rel) & 1u)
                __stcs(reinterpret_cast<float2*>(
                           g_xw + (size_t)grow0 * 512 + rel * 64 + e),
                       *reinterpret_cast<float2*>(&s0));
            if ((m1 >> rel) & 1u)
                __stcs(reinterpret_cast<float2*>(
                           g_xw + (size_t)(grow0 + 8) * 512 + rel * 64 + e),
                       *reinterpret_cast<float2*>(&s1));
        }
    }

    // ---- root columns -> g_agg (+bias) ----
    const float* sb = reinterpret_cast<const float*>(sm + SM_BIASO);
#pragma unroll
    for (int nt = 0; nt < 8; nt++) {
        float acc[4] = {0.f, 0.f, 0.f, 0.f};
#pragma unroll
        for (int ks = 0; ks < 4; ks++) {
            int kb2 = (ks * 16 + 2 * j) * 2;
            int n = 256 + nt * 8 + g;
            const char* wh = sm + SM_WHI + n * 144 + kb2;
            const char* wl = sm + SM_WLO + n * 144 + kb2;
            uint32_t bh0 = *reinterpret_cast<const uint32_t*>(wh);
            uint32_t bh1 = *reinterpret_cast<const uint32_t*>(wh + 16);
            uint32_t bl0 = *reinterpret_cast<const uint32_t*>(wl);
            uint32_t bl1 = *reinterpret_cast<const uint32_t*>(wl + 16);
            MMA_BF16(acc, Ah[ks], bh0, bh1);
            MMA_BF16(acc, Ah[ks], bl0, bl1);
            MMA_BF16(acc, Al[ks], bh0, bh1);
        }
        int e = nt * 8 + 2 * j;
        float b0 = sb[e], b1 = sb[e + 1];
        if (grow0 < NNODE) {
            float2 v = make_float2(acc[0] + b0, acc[1] + b1);
            *reinterpret_cast<float2*>(g_agg + (size_t)grow0 * 64 + e) = v;
        }
        if (grow0 + 8 < NNODE) {
            float2 v = make_float2(acc[2] + b0, acc[3] + b1);
            *reinterpret_cast<float2*>(g_agg + (size_t)(grow0 + 8) * 64 + e) = v;
        }
    }
}

// =====================================================================
// edge_csr: 16 lanes per dst node. acc = g_agg[d] (root+bias), then
// gather+sum xw[src][et] over the dst's incoming edges (4-deep pipeline),
// tanh, write straight into g_cs. No atomics, no finish kernel.
// =====================================================================
__device__ __forceinline__ float4 xw_row(unsigned pk, int j) {
    return __ldcs(reinterpret_cast<const float4*>(
        g_xw + (size_t)(pk & 0xFFFFFu) * 512 + ((pk >> 20) & 7u) * 64 + j * 4));
}

__global__ __launch_bounds__(256) void edge_csr(int rbase, int loff)
{
    int grp = blockIdx.x * 16 + (threadIdx.x >> 4);
    if (grp >= NNODE) return;
    int j = threadIdx.x & 15;

    int beg = __ldg(&g_rowptr[rbase + grp]);
    int end = __ldg(&g_rowptr[rbase + grp + 1]);

    float4 acc = *reinterpret_cast<const float4*>(g_agg + (size_t)grp * 64 + j * 4);

    int e = beg;
    for (; e + 4 <= end; e += 4) {
        unsigned p0 = __ldg(&g_epack[e]);
        unsigned p1 = __ldg(&g_epack[e + 1]);
        unsigned p2 = __ldg(&g_epack[e + 2]);
        unsigned p3 = __ldg(&g_epack[e + 3]);
        float4 v0 = xw_row(p0, j);
        float4 v1 = xw_row(p1, j);
        float4 v2 = xw_row(p2, j);
        float4 v3 = xw_row(p3, j);
        acc.x += (v0.x + v1.x) + (v2.x + v3.x);
        acc.y += (v0.y + v1.y) + (v2.y + v3.y);
        acc.z += (v0.z + v1.z) + (v2.z + v3.z);
        acc.w += (v0.w + v1.w) + (v2.w + v3.w);
    }
    for (; e < end; ++e) {
        float4 v = xw_row(__ldg(&g_epack[e]), j);
        acc.x += v.x; acc.y += v.y; acc.z += v.z; acc.w += v.w;
    }

    acc.x = tanhf(acc.x); acc.y = tanhf(acc.y);
    acc.z = tanhf(acc.z); acc.w = tanhf(acc.w);
    *reinterpret_cast<float4*>(g_cs + (size_t)grp * TDIM + loff + j * 4) = acc;
}

// =====================================================================
// Tail A: gather item_embs_conv + user_emb outputs, build sequence sums.
// =====================================================================
__global__ __launch_bounds__(TDIM) void tail_a(
    const int* __restrict__ users,
    const int* __restrict__ seqs,
    float* __restrict__ out_user,
    float* __restrict__ out_item)
{
    int b = blockIdx.x;
    int t = threadIdx.x;
    float s = 0.f;
#pragma unroll
    for (int j = 0; j < SEQ; j++) {
        int node = __ldg(&seqs[b * SEQ + j]);
        float v  = __ldg(&g_cs[(size_t)node * TDIM + t]);
        out_item[((size_t)b * SEQ + j) * TDIM + t] = v;
        s += v;
    }
    g_ssum[b * TDIM + t] = s;
    int u = __ldg(&users[b]);
    out_user[b * TDIM + t] = __ldg(&g_cs[(size_t)u * TDIM + t]);
}

// =====================================================================
// tb_uv: uv = user_emb + ssum @ WV.  8 batches per block.
// (attention collapses: softmax over query axis => column sums == 1)
// =====================================================================
__global__ __launch_bounds__(TDIM) void tb_uv(
    const float* __restrict__ WV,
    const float* __restrict__ user_emb)
{
    __shared__ float ss[8 * TDIM];
    int b0 = blockIdx.x * 8;
    int t  = threadIdx.x;

#pragma unroll
    for (int i = 0; i < 8; i++)
        ss[i * TDIM + t] = g_ssum[(b0 + i) * TDIM + t];
    __syncthreads();

    float acc[8];
#pragma unroll
    for (int i = 0; i < 8; i++) acc[i] = 0.f;

#pragma unroll 4
    for (int k = 0; k < TDIM; ++k) {
        float w = __ldg(&WV[k * TDIM + t]);
#pragma unroll
        for (int i = 0; i < 8; i++) acc[i] = fmaf(ss[i * TDIM + k], w, acc[i]);
    }
#pragma unroll
    for (int i = 0; i < 8; i++)
        g_uv[(b0 + i) * TDIM + t] = acc[i] + user_emb[(b0 + i) * TDIM + t];
}

// =====================================================================
// tb_res: res[b,k] = pe_w[item]·uv[b] + pe_b[item]
// =====================================================================
__global__ __launch_bounds__(TDIM) void tb_res(
    const float* __restrict__ predict_w,
    const float* __restrict__ predict_b,
    const int*   __restrict__ items,
    float* __restrict__ res)
{
    __shared__ float uv[TDIM];
    int b = blockIdx.x;
    int t = threadIdx.x;
    uv[t] = g_uv[b * TDIM + t];
    __syncthreads();

    int w    = t >> 5;
    int lane = t & 31;
    for (int k = w; k < NPRED; k += TDIM / 32) {
        int it = __ldg(&items[b * NPRED + k]);
        const float* pw = predict_w + (size_t)it * TDIM;
        float s = 0.f;
#pragma unroll
        for (int c = lane; c < TDIM; c += 32) s += __ldg(&pw[c]) * uv[c];
#pragma unroll
        for (int off = 16; off > 0; off >>= 1)
            s += __shfl_down_sync(0xffffffffu, s, off);
        if (lane == 0)
            res[b * NPRED + k] = s + __ldg(&predict_b[it]);
    }
}

// =====================================================================
// Launch
// =====================================================================
extern "C" void kernel_launch(void* const* d_in, const int* in_sizes, int n_in,
                              void* d_out, int out_size)
{
    const float* node_emb  = (const float*)d_in[0];
    const float* predict_w = (const float*)d_in[1];
    const float* predict_b = (const float*)d_in[2];
    const float* basis     = (const float*)d_in[3];
    const float* comp      = (const float*)d_in[4];
    const float* root      = (const float*)d_in[5];
    const float* bias      = (const float*)d_in[6];
    const float* sbasis    = (const float*)d_in[7];
    const float* scomp     = (const float*)d_in[8];
    const float* sroot     = (const float*)d_in[9];
    const float* sbias     = (const float*)d_in[10];
    // d_in[11] = WQ, d_in[12] = WK : provably unused (softmax over query axis)
    const float* WV        = (const float*)d_in[13];
    const int* batch_users = (const int*)d_in[14];
    const int* batch_seq   = (const int*)d_in[15];
    const int* items       = (const int*)d_in[16];
    const int* edge_index  = (const int*)d_in[17];
    const int* edge_type   = (const int*)d_in[18];
    // d_in[19] = node_no (identity gather, unused)
    const int* sedge_index = (const int*)d_in[20];
    const int* sedge_type  = (const int*)d_in[21];

    const int E  = in_sizes[18];   // 1,000,000
    const int SE = in_sizes[21];   //   200,000

    const int* srcB = edge_index;
    const int* dstB = edge_index + E;
    const int* srcS = sedge_index;
    const int* dstS = sedge_index + SE;

    float* out_res  = (float*)d_out;                       // [1024][20]
    float* out_user = out_res + BATCH * NPRED;             // [1024][384]
    float* out_item = out_user + BATCH * TDIM;             // [1024][20][384]

    cudaFuncSetAttribute(tc_dense,
                         cudaFuncAttributeMaxDynamicSharedMemorySize, TC_SMEM);

    // ---- one-time prep: W images + relation masks + CSR ----
    w_prep_all<<<480, 256>>>(basis, root, sbasis, sroot);
    rmask_zero<<<(2 * NNODE + 1023) / 1024, 1024>>>();
    rmask_build<<<(E + SE + 255) / 256, 256>>>(srcB, edge_type, srcS, sedge_type, E, SE);
    csr_zero<<<NSCANB, 1024>>>();
    csr_hist<<<(E + SE + 255) / 256, 256>>>(dstB, dstS, E, SE);
    csr_scan1<<<NSCANB, 1024>>>();
    csr_scan2<<<1, 32>>>();
    csr_scan3<<<NSCANB, 1024>>>();
    csr_scatter<<<(E + SE + 255) / 256, 256>>>(srcB, dstB, edge_type,
                                               srcS, dstS, sedge_type, E, SE);

    const int tc_grid  = (NNODE + 255) / 256;              // 586
    const int csr_grid = (NNODE + 15) / 16;                // 9375

    for (int l = 0; l < 6; ++l) {
        bool big = (l < 3);
        int  ll  = big ? l : l - 3;
        const float* Bi = (big ? bias : sbias) + ll * 64;
        const float* C  = (big ? comp : scomp) + ll * 32;
        const float* xi = (l == 0) ? node_emb : nullptr;
        int rbase       = big ? 0 : (NNODE + 1);
        int gsel        = big ? 0 : 1;

        tc_dense<<<tc_grid, 512, TC_SMEM>>>(xi, l, gsel, C, Bi);
        edge_csr<<<csr_grid, 256>>>(rbase, l * 64);
    }

    tail_a<<<BATCH, TDIM>>>(batch_users, batch_seq, out_user, out_item);
    tb_uv<<<BATCH / 8, TDIM>>>(WV, out_user);
    tb_res<<<BATCH, TDIM>>>(predict_w, predict_b, items, out_res);
}